// round 14
// baseline (speedup 1.0000x reference)
#include <cuda_runtime.h>
#include <cuda_bf16.h>
#include <cuda_fp16.h>
#include <math.h>
#include <stdint.h>

// Problem constants (fixed by the benchmark shapes)
#define BB   4
#define NN   16384
#define CC   256
#define C3   768
#define TT   64
#define HH   8
#define DD   32
#define GS   128
#define NG   128
#define NCH  128
#define CHSZ 128

// -------- scratch (device globals) --------
__device__ int   g_tkid[BB * NN];
__device__ int   g_sortidx[BB * NN];
__device__ int   g_hist[BB * TT * NCH];
__device__ __half g_y[(size_t)BB * NN * CC];     // attention out, single fp16 plane
__device__ __half g_w[CC * CC];                  // W fp16 (1-term)

// ---------------- PTX helpers ----------------
__device__ __forceinline__ uint32_t smem_u32(const void* p) {
    return (uint32_t)__cvta_generic_to_shared(p);
}
__device__ __forceinline__ void ldm_x4(uint32_t* r, uint32_t a) {
    asm volatile("ldmatrix.sync.aligned.m8n8.x4.shared.b16 {%0,%1,%2,%3},[%4];"
                 : "=r"(r[0]), "=r"(r[1]), "=r"(r[2]), "=r"(r[3]) : "r"(a));
}
__device__ __forceinline__ void ldm_x4_t(uint32_t* r, uint32_t a) {
    asm volatile("ldmatrix.sync.aligned.m8n8.x4.trans.shared.b16 {%0,%1,%2,%3},[%4];"
                 : "=r"(r[0]), "=r"(r[1]), "=r"(r[2]), "=r"(r[3]) : "r"(a));
}
__device__ __forceinline__ void mma_bf16(float* c, const uint32_t* a, uint32_t b0, uint32_t b1) {
    asm volatile(
        "mma.sync.aligned.m16n8k16.row.col.f32.bf16.bf16.f32 "
        "{%0,%1,%2,%3},{%4,%5,%6,%7},{%8,%9},{%0,%1,%2,%3};"
        : "+f"(c[0]), "+f"(c[1]), "+f"(c[2]), "+f"(c[3])
        : "r"(a[0]), "r"(a[1]), "r"(a[2]), "r"(a[3]), "r"(b0), "r"(b1));
}
__device__ __forceinline__ void mma_f16(float* c, const uint32_t* a, uint32_t b0, uint32_t b1) {
    asm volatile(
        "mma.sync.aligned.m16n8k16.row.col.f32.f16.f16.f32 "
        "{%0,%1,%2,%3},{%4,%5,%6,%7},{%8,%9},{%0,%1,%2,%3};"
        : "+f"(c[0]), "+f"(c[1]), "+f"(c[2]), "+f"(c[3])
        : "r"(a[0]), "r"(a[1]), "r"(a[2]), "r"(a[3]), "r"(b0), "r"(b1));
}
__device__ __forceinline__ uint32_t packh2(float x, float y) {
    __half2 t = __floats2half2_rn(x, y);
    return *(uint32_t*)&t;
}
__device__ __forceinline__ void cp16(void* smem_dst, const void* gsrc) {
    asm volatile("cp.async.cg.shared.global [%0], [%1], 16;"
                 :: "r"(smem_u32(smem_dst)), "l"(gsrc));
}
#define CP_COMMIT()  asm volatile("cp.async.commit_group;")
#define CP_WAIT(N)   asm volatile("cp.async.wait_group %0;" :: "n"(N))

extern __shared__ __align__(16) char dynsm[];

// ---------------- 1+2a) fused argmax + histogram + W fp16 convert ----------------
__global__ void k_argmax_hist(const float* __restrict__ sim, const float* __restrict__ W) {
    __shared__ int h[TT];
    int b  = blockIdx.x / NCH;
    int ch = blockIdx.x % NCH;
    int t  = threadIdx.x;
    {
        int wi = blockIdx.x * CHSZ + t;
        g_w[wi] = __float2half_rn(W[wi]);
    }
    if (t < TT) h[t] = 0;
    int idx = b * NN + ch * CHSZ + t;
    const float4* p = (const float4*)(sim + (size_t)idx * TT);
    float best = -3.402823466e38f;
    int bi = 0;
#pragma unroll
    for (int i = 0; i < 16; i++) {
        float4 v = p[i];
        if (v.x > best) { best = v.x; bi = 4 * i + 0; }
        if (v.y > best) { best = v.y; bi = 4 * i + 1; }
        if (v.z > best) { best = v.z; bi = 4 * i + 2; }
        if (v.w > best) { best = v.w; bi = 4 * i + 3; }
    }
    g_tkid[idx] = bi;
    __syncthreads();
    atomicAdd(&h[bi], 1);
    __syncthreads();
    if (t < TT)
        g_hist[(b * TT + t) * NCH + ch] = h[t];
}

// ---------------- 2b+2c) fused scan + stable scatter ----------------
// Block per (b, chunk). Each block redundantly computes the exclusive scan of
// its batch's full [TT x NCH] histogram in smem (parallel: 64 elems/thread +
// shfl warp-scan of partials), then scatters its 128 tokens with match/ballot
// ranks. Removes the serialized 4-block k_scan kernel entirely.
__global__ void k_scatter2() {
    __shared__ int hs[TT * NCH];       // 8192 ints = 32 KB
    __shared__ int psum[4];
    __shared__ int whist[4][TT];
    int b  = blockIdx.x / NCH;
    int ch = blockIdx.x % NCH;
    int t  = threadIdx.x;
    int lane = t & 31, w = t >> 5;

    // load batch histogram (vectorized) + zero whist
    {
        const int4* src = (const int4*)(g_hist + b * TT * NCH);
        int4* dst = (int4*)hs;
#pragma unroll
        for (int i = 0; i < (TT * NCH / 4) / 128; i++)
            dst[t + i * 128] = src[t + i * 128];
    }
    ((int*)whist)[t] = 0;
    ((int*)whist)[t + 128] = 0;
    __syncthreads();

    // thread-local sum over 64 contiguous elements
    int s = 0;
#pragma unroll
    for (int i = 0; i < 64; i++) s += hs[t * 64 + i];
    // warp inclusive scan of the 128 partials
    int inc = s;
#pragma unroll
    for (int d = 1; d < 32; d <<= 1) {
        int x = __shfl_up_sync(0xffffffffu, inc, d);
        if (lane >= d) inc += x;
    }
    if (lane == 31) psum[w] = inc;
    __syncthreads();
    int woff = 0;
#pragma unroll
    for (int w2 = 0; w2 < 3; w2++)
        if (w2 < w) woff += psum[w2];
    int ex = woff + inc - s;           // exclusive prefix at this thread's segment
#pragma unroll
    for (int i = 0; i < 64; i++) {
        int x = hs[t * 64 + i];
        hs[t * 64 + i] = ex;
        ex += x;
    }

    // match/ballot stable ranks within the chunk
    int key = g_tkid[b * NN + ch * CHSZ + t];
    unsigned mask = __match_any_sync(0xffffffffu, key);
    int wrank = __popc(mask & ((1u << lane) - 1u));
    if (lane == (__ffs(mask) - 1))
        whist[w][key] = __popc(mask);
    __syncthreads();
    int off = 0;
#pragma unroll
    for (int w2 = 0; w2 < 3; w2++)
        if (w2 < w) off += whist[w2][key];
    int pos = hs[key * NCH + ch] + off + wrank;
    g_sortidx[b * NN + pos] = ch * CHSZ + t;
}

// ---------------- 3) tensor-core attention, flash-chunked (R11/R13 config) ----------------
// Grid = (HH, NG, BB): h fastest so sibling head-blocks co-run and tile each
// token's contiguous 3KB row across L2.
// 256 threads = 8 warps, warp owns 16 query rows. Flash chunks of 64 cols.
// Gather: wavefront-minimal (8 lanes per 128B token-slice).
// QK: bf16x3. PV: fp16. Output y: single fp16 plane.
#define AST 40
#define SM_Q_HI 0
#define SM_Q_LO (128 * AST)
#define SM_K_HI (2 * 128 * AST)
#define SM_K_LO (3 * 128 * AST)
#define SM_VF   (4 * 128 * AST)
#define SM_TOK  (5 * 128 * AST)
#define SMEM_ATT_BYTES (5 * 128 * AST * 2 + 128 * 4)

__global__ void __launch_bounds__(256, 3)
k_attn_mma(const float* __restrict__ qkv, const float* __restrict__ logit_scale) {
    __nv_bfloat16* sm = (__nv_bfloat16*)dynsm;
    __nv_bfloat16* Qh = sm + SM_Q_HI;
    __nv_bfloat16* Ql = sm + SM_Q_LO;
    __nv_bfloat16* Kh = sm + SM_K_HI;
    __nv_bfloat16* Kl = sm + SM_K_LO;
    __half*        Vf = (__half*)(sm + SM_VF);
    int* toks = (int*)(sm + SM_TOK);

    int h = blockIdx.x, g = blockIdx.y, b = blockIdx.z;
    int tid = threadIdx.x, lane = tid & 31, warp = tid >> 5;

    // ---- stage sorted token ids ----
    if (tid < GS) toks[tid] = g_sortidx[b * NN + g * GS + tid];
    __syncthreads();

    // ---- wavefront-minimal gather ----
    {
        const float* qb = qkv + (size_t)b * NN * C3 + h * DD;
        int rsub  = tid & 7;
        int rbase = tid >> 3;                       // 0..31
#pragma unroll
        for (int tsel = 0; tsel < 3; tsel++) {
            int rw[4];
            const float4* ap[4];
#pragma unroll
            for (int i2 = 0; i2 < 4; i2++) {
                rw[i2] = i2 * 32 + rbase;
                ap[i2] = (const float4*)(qb + (size_t)toks[rw[i2]] * C3 + tsel * CC + rsub * 4);
            }
#pragma unroll
            for (int i2 = 0; i2 < 4; i2++) {
                float4 x = *ap[i2];
                int row = rw[i2];
                if (tsel < 2) {
                    __nv_bfloat162 h01 = __floats2bfloat162_rn(x.x, x.y);
                    __nv_bfloat162 h23 = __floats2bfloat162_rn(x.z, x.w);
                    float2 f01 = __bfloat1622float2(h01);
                    float2 f23 = __bfloat1622float2(h23);
                    __nv_bfloat162 l01 = __floats2bfloat162_rn(x.x - f01.x, x.y - f01.y);
                    __nv_bfloat162 l23 = __floats2bfloat162_rn(x.z - f23.x, x.w - f23.y);
                    __nv_bfloat16* dh = (tsel == 0 ? Qh : Kh) + row * AST + rsub * 4;
                    __nv_bfloat16* dl = (tsel == 0 ? Ql : Kl) + row * AST + rsub * 4;
                    *(uint2*)dh = make_uint2(*(uint32_t*)&h01, *(uint32_t*)&h23);
                    *(uint2*)dl = make_uint2(*(uint32_t*)&l01, *(uint32_t*)&l23);
                } else {
                    __half2 p01 = __floats2half2_rn(x.x, x.y);
                    __half2 p23 = __floats2half2_rn(x.z, x.w);
                    *(uint2*)(Vf + row * AST + rsub * 4) =
                        make_uint2(*(uint32_t*)&p01, *(uint32_t*)&p23);
                }
            }
        }
    }
    // fold softmax scale and log2(e): p = exp2(s*sc2 - M2)
    float sc2 = __expf(fminf(logit_scale[0], 4.605170185988091f)) * 1.44269504088896f;
    __syncthreads();

    int m0 = warp * 16;
    int l16 = lane & 15;

    uint32_t qh[2][4];
#pragma unroll
    for (int ks = 0; ks < 2; ks++)
        ldm_x4(qh[ks], smem_u32(Qh + (m0 + l16) * AST + ks * 16 + (lane >> 4) * 8));

    float o[4][4];
#pragma unroll
    for (int nf = 0; nf < 4; nf++)
#pragma unroll
        for (int r = 0; r < 4; r++) o[nf][r] = 0.0f;
    float m01 = -1e30f, m23 = -1e30f, l01 = 0.0f, l23 = 0.0f;

#pragma unroll
    for (int chnk = 0; chnk < 2; chnk++) {
        int c0 = chnk * 64;
        uint32_t ql[2][4];
#pragma unroll
        for (int ks = 0; ks < 2; ks++)
            ldm_x4(ql[ks], smem_u32(Ql + (m0 + l16) * AST + ks * 16 + (lane >> 4) * 8));

        float s[8][4];
#pragma unroll
        for (int nf = 0; nf < 8; nf++)
#pragma unroll
            for (int r = 0; r < 4; r++) s[nf][r] = 0.0f;

#pragma unroll
        for (int p2 = 0; p2 < 4; p2++) {
            int j0 = c0 + p2 * 16;
#pragma unroll
            for (int ks = 0; ks < 2; ks++) {
                uint32_t kb[4], kl4[4];
                int krow = j0 + ((lane >> 4) << 3) + (lane & 7);
                int kcol = ks * 16 + ((lane >> 3) & 1) * 8;
                ldm_x4(kb,  smem_u32(Kh + krow * AST + kcol));
                ldm_x4(kl4, smem_u32(Kl + krow * AST + kcol));
                mma_bf16(s[2 * p2],     qh[ks], kb[0],  kb[1]);
                mma_bf16(s[2 * p2],     qh[ks], kl4[0], kl4[1]);
                mma_bf16(s[2 * p2],     ql[ks], kb[0],  kb[1]);
                mma_bf16(s[2 * p2 + 1], qh[ks], kb[2],  kb[3]);
                mma_bf16(s[2 * p2 + 1], qh[ks], kl4[2], kl4[3]);
                mma_bf16(s[2 * p2 + 1], ql[ks], kb[2],  kb[3]);
            }
        }

        // scale fold + chunk row-max (quad shfl)
        float cm01 = -1e30f, cm23 = -1e30f;
#pragma unroll
        for (int nf = 0; nf < 8; nf++) {
#pragma unroll
            for (int r = 0; r < 4; r++) s[nf][r] *= sc2;
            cm01 = fmaxf(cm01, fmaxf(s[nf][0], s[nf][1]));
            cm23 = fmaxf(cm23, fmaxf(s[nf][2], s[nf][3]));
        }
        cm01 = fmaxf(cm01, __shfl_xor_sync(0xffffffffu, cm01, 1));
        cm01 = fmaxf(cm01, __shfl_xor_sync(0xffffffffu, cm01, 2));
        cm23 = fmaxf(cm23, __shfl_xor_sync(0xffffffffu, cm23, 1));
        cm23 = fmaxf(cm23, __shfl_xor_sync(0xffffffffu, cm23, 2));

        // online update
        float nm01 = fmaxf(m01, cm01), nm23 = fmaxf(m23, cm23);
        float cor01 = exp2f(m01 - nm01), cor23 = exp2f(m23 - nm23);
        m01 = nm01; m23 = nm23;
#pragma unroll
        for (int nf = 0; nf < 4; nf++) {
            o[nf][0] *= cor01; o[nf][1] *= cor01;
            o[nf][2] *= cor23; o[nf][3] *= cor23;
        }

        float sum01 = 0.0f, sum23 = 0.0f;
#pragma unroll
        for (int nf = 0; nf < 8; nf++) {
            float e0 = exp2f(s[nf][0] - m01);
            float e1 = exp2f(s[nf][1] - m01);
            float e2 = exp2f(s[nf][2] - m23);
            float e3 = exp2f(s[nf][3] - m23);
            s[nf][0] = e0; s[nf][1] = e1; s[nf][2] = e2; s[nf][3] = e3;
            sum01 += e0 + e1;
            sum23 += e2 + e3;
        }
        sum01 += __shfl_xor_sync(0xffffffffu, sum01, 1);
        sum01 += __shfl_xor_sync(0xffffffffu, sum01, 2);
        sum23 += __shfl_xor_sync(0xffffffffu, sum23, 1);
        sum23 += __shfl_xor_sync(0xffffffffu, sum23, 2);
        l01 = l01 * cor01 + sum01;
        l23 = l23 * cor23 + sum23;

        // PV over this chunk's 64 k-rows
#pragma unroll
        for (int kj = 0; kj < 4; kj++) {
            int f0 = 2 * kj, f1 = 2 * kj + 1;
            uint32_t ph[4];
            ph[0] = packh2(s[f0][0], s[f0][1]);
            ph[1] = packh2(s[f0][2], s[f0][3]);
            ph[2] = packh2(s[f1][0], s[f1][1]);
            ph[3] = packh2(s[f1][2], s[f1][3]);
            int vrow = c0 + kj * 16 + l16;
#pragma unroll
            for (int dh2 = 0; dh2 < 2; dh2++) {
                uint32_t vf[4];
                ldm_x4_t(vf, smem_u32(Vf + vrow * AST + dh2 * 16 + ((lane >> 4) << 3)));
                mma_f16(o[2 * dh2],     ph, vf[0], vf[1]);
                mma_f16(o[2 * dh2 + 1], ph, vf[2], vf[3]);
            }
        }
    }

    // ---- epilogue: normalize, fp16, scatter to original token rows ----
    float inv0 = 1.0f / l01, inv1 = 1.0f / l23;
    int r0 = m0 + (lane >> 2);
    int tok0 = toks[r0], tok1 = toks[r0 + 8];
    size_t ob0 = (size_t)(b * NN + tok0) * CC + h * DD + (lane & 3) * 2;
    size_t ob1 = (size_t)(b * NN + tok1) * CC + h * DD + (lane & 3) * 2;
#pragma unroll
    for (int nf = 0; nf < 4; nf++) {
        *(__half2*)(g_y + ob0 + nf * 8) = __floats2half2_rn(o[nf][0] * inv0, o[nf][1] * inv0);
        *(__half2*)(g_y + ob1 + nf * 8) = __floats2half2_rn(o[nf][2] * inv1, o[nf][3] * inv1);
    }
}

// ---------------- 4) projection: fp16 1-term MMA, cp.async double-buffered ----------------
#define PST  40
#define PPL  (128 * PST)
#define PSTG (2 * PPL)
#define SMEM_PROJ_BYTES (2 * PSTG * 2)

__global__ void __launch_bounds__(256)
k_proj2(const float* __restrict__ bias, float* __restrict__ out) {
    __half* sm = (__half*)dynsm;

    int tid  = threadIdx.x;
    int lane = tid & 31;
    int warp = tid >> 5;
    int row0 = blockIdx.x * 128;
    int col0 = blockIdx.y * 128;
    int m_off = (warp & 3) * 32;
    int n_off = (warp >> 2) * 64;
    int l16 = lane & 15;

    int c0 = tid * 2;
    int rA0 = c0 >> 2, qA0 = (c0 & 3) * 8;
    int rA1 = (c0 + 1) >> 2, qA1 = ((c0 + 1) & 3) * 8;

    const __half* gA = g_y + (size_t)row0 * CC;
    const __half* gB = g_w + (size_t)col0 * CC;

    auto load_stage = [&](int st, int k0) {
        __half* Af = sm + st * PSTG;
        __half* Bf = Af + PPL;
        cp16(Af + rA0 * PST + qA0, gA + (size_t)rA0 * CC + k0 + qA0);
        cp16(Af + rA1 * PST + qA1, gA + (size_t)rA1 * CC + k0 + qA1);
        cp16(Bf + rA0 * PST + qA0, gB + (size_t)rA0 * CC + k0 + qA0);
        cp16(Bf + rA1 * PST + qA1, gB + (size_t)rA1 * CC + k0 + qA1);
        CP_COMMIT();
    };

    float c[2][8][4];
#pragma unroll
    for (int mf = 0; mf < 2; mf++)
#pragma unroll
        for (int nf = 0; nf < 8; nf++)
#pragma unroll
            for (int r = 0; r < 4; r++) c[mf][nf][r] = 0.0f;

    load_stage(0, 0);

    for (int kt = 0; kt < 8; kt++) {
        if (kt + 1 < 8) {
            load_stage((kt + 1) & 1, (kt + 1) * 32);
            CP_WAIT(1);
        } else {
            CP_WAIT(0);
        }
        __syncthreads();

        __half* Af = sm + (kt & 1) * PSTG;
        __half* Bf = Af + PPL;

#pragma unroll
        for (int kk = 0; kk < 32; kk += 16) {
            uint32_t bh[8][2];
#pragma unroll
            for (int np = 0; np < 4; np++) {
                uint32_t t4[4];
                int brow = n_off + np * 16 + ((lane >> 4) << 3) + (lane & 7);
                int bcol = kk + ((lane >> 3) & 1) * 8;
                ldm_x4(t4, smem_u32(Bf + brow * PST + bcol));
                bh[2 * np][0] = t4[0]; bh[2 * np][1] = t4[1];
                bh[2 * np + 1][0] = t4[2]; bh[2 * np + 1][1] = t4[3];
            }
#pragma unroll
            for (int mf = 0; mf < 2; mf++) {
                uint32_t af[4];
                int arow = m_off + mf * 16 + l16;
                ldm_x4(af, smem_u32(Af + arow * PST + kk + (lane >> 4) * 8));
#pragma unroll
                for (int nf = 0; nf < 8; nf++)
                    mma_f16(c[mf][nf], af, bh[nf][0], bh[nf][1]);
            }
        }
        __syncthreads();
    }

#pragma unroll
    for (int mf = 0; mf < 2; mf++) {
#pragma unroll
        for (int nf = 0; nf < 8; nf++) {
            int rg = row0 + m_off + mf * 16 + (lane >> 2);
            int cg = col0 + n_off + nf * 8 + (lane & 3) * 2;
            float b0 = bias[cg], b1 = bias[cg + 1];
            float2* o0 = (float2*)(out + (size_t)rg * CC + cg);
            float2* o1 = (float2*)(out + (size_t)(rg + 8) * CC + cg);
            *o0 = make_float2(c[mf][nf][0] + b0, c[mf][nf][1] + b1);
            *o1 = make_float2(c[mf][nf][2] + b0, c[mf][nf][3] + b1);
        }
    }
}

// ---------------- launch ----------------
extern "C" void kernel_launch(void* const* d_in, const int* in_sizes, int n_in,
                              void* d_out, int out_size) {
    const float* qkv         = (const float*)d_in[0];
    const float* sim         = (const float*)d_in[1];
    const float* proj_w      = (const float*)d_in[2];
    const float* proj_b      = (const float*)d_in[3];
    const float* logit_scale = (const float*)d_in[4];
    float* out = (float*)d_out;

    k_argmax_hist<<<BB * NCH, CHSZ>>>(sim, proj_w);
    k_scatter2<<<BB * NCH, CHSZ>>>();           // fused scan + scatter

    // h fastest: 8 sibling head-blocks of one (b,g) co-run and share token rows in L2
    cudaFuncSetAttribute(k_attn_mma, cudaFuncAttributeMaxDynamicSharedMemorySize, SMEM_ATT_BYTES);
    k_attn_mma<<<dim3(HH, NG, BB), 256, SMEM_ATT_BYTES>>>(qkv, logit_scale);

    cudaFuncSetAttribute(k_proj2, cudaFuncAttributeMaxDynamicSharedMemorySize, SMEM_PROJ_BYTES);
    k_proj2<<<dim3((BB * NN) / 128, CC / 128), 256, SMEM_PROJ_BYTES>>>(proj_b, out);
}

// round 15
// speedup vs baseline: 1.1279x; 1.1279x over previous
#include <cuda_runtime.h>
#include <cuda_bf16.h>
#include <cuda_fp16.h>
#include <math.h>
#include <stdint.h>

// Problem constants (fixed by the benchmark shapes)
#define BB   4
#define NN   16384
#define CC   256
#define C3   768
#define TT   64
#define HH   8
#define DD   32
#define GS   128
#define NG   128
#define NCH  128
#define CHSZ 128

// -------- scratch (device globals) --------
__device__ int   g_tkid[BB * NN];
__device__ int   g_sortidx[BB * NN];
__device__ int   g_hist[BB * TT * NCH];
__device__ __half g_y[(size_t)BB * NN * CC];     // attention out, single fp16 plane
__device__ __half g_w[CC * CC];                  // W fp16 (1-term)

// ---------------- PTX helpers ----------------
__device__ __forceinline__ uint32_t smem_u32(const void* p) {
    return (uint32_t)__cvta_generic_to_shared(p);
}
__device__ __forceinline__ void ldm_x4(uint32_t* r, uint32_t a) {
    asm volatile("ldmatrix.sync.aligned.m8n8.x4.shared.b16 {%0,%1,%2,%3},[%4];"
                 : "=r"(r[0]), "=r"(r[1]), "=r"(r[2]), "=r"(r[3]) : "r"(a));
}
__device__ __forceinline__ void ldm_x4_t(uint32_t* r, uint32_t a) {
    asm volatile("ldmatrix.sync.aligned.m8n8.x4.trans.shared.b16 {%0,%1,%2,%3},[%4];"
                 : "=r"(r[0]), "=r"(r[1]), "=r"(r[2]), "=r"(r[3]) : "r"(a));
}
__device__ __forceinline__ void mma_bf16(float* c, const uint32_t* a, uint32_t b0, uint32_t b1) {
    asm volatile(
        "mma.sync.aligned.m16n8k16.row.col.f32.bf16.bf16.f32 "
        "{%0,%1,%2,%3},{%4,%5,%6,%7},{%8,%9},{%0,%1,%2,%3};"
        : "+f"(c[0]), "+f"(c[1]), "+f"(c[2]), "+f"(c[3])
        : "r"(a[0]), "r"(a[1]), "r"(a[2]), "r"(a[3]), "r"(b0), "r"(b1));
}
__device__ __forceinline__ void mma_f16(float* c, const uint32_t* a, uint32_t b0, uint32_t b1) {
    asm volatile(
        "mma.sync.aligned.m16n8k16.row.col.f32.f16.f16.f32 "
        "{%0,%1,%2,%3},{%4,%5,%6,%7},{%8,%9},{%0,%1,%2,%3};"
        : "+f"(c[0]), "+f"(c[1]), "+f"(c[2]), "+f"(c[3])
        : "r"(a[0]), "r"(a[1]), "r"(a[2]), "r"(a[3]), "r"(b0), "r"(b1));
}
__device__ __forceinline__ uint32_t packh2(float x, float y) {
    __half2 t = __floats2half2_rn(x, y);
    return *(uint32_t*)&t;
}
__device__ __forceinline__ void cp16(void* smem_dst, const void* gsrc) {
    asm volatile("cp.async.cg.shared.global [%0], [%1], 16;"
                 :: "r"(smem_u32(smem_dst)), "l"(gsrc));
}
#define CP_COMMIT()  asm volatile("cp.async.commit_group;")
#define CP_WAIT(N)   asm volatile("cp.async.wait_group %0;" :: "n"(N))

extern __shared__ __align__(16) char dynsm[];

// ---------------- 1+2a) fused argmax + histogram + W fp16 convert ----------------
__global__ void k_argmax_hist(const float* __restrict__ sim, const float* __restrict__ W) {
    __shared__ int h[TT];
    int b  = blockIdx.x / NCH;
    int ch = blockIdx.x % NCH;
    int t  = threadIdx.x;
    {
        int wi = blockIdx.x * CHSZ + t;
        g_w[wi] = __float2half_rn(W[wi]);
    }
    if (t < TT) h[t] = 0;
    int idx = b * NN + ch * CHSZ + t;
    const float4* p = (const float4*)(sim + (size_t)idx * TT);
    float best = -3.402823466e38f;
    int bi = 0;
#pragma unroll
    for (int i = 0; i < 16; i++) {
        float4 v = p[i];
        if (v.x > best) { best = v.x; bi = 4 * i + 0; }
        if (v.y > best) { best = v.y; bi = 4 * i + 1; }
        if (v.z > best) { best = v.z; bi = 4 * i + 2; }
        if (v.w > best) { best = v.w; bi = 4 * i + 3; }
    }
    g_tkid[idx] = bi;
    __syncthreads();
    atomicAdd(&h[bi], 1);
    __syncthreads();
    if (t < TT)
        g_hist[(b * TT + t) * NCH + ch] = h[t];
}

// ---------------- 2b) exclusive scan ----------------
__global__ void k_scan() {
    __shared__ int tot[256];
    int b = blockIdx.x;
    int* base = g_hist + b * TT * NCH;
    int t = threadIdx.x;
    int v[32];
    int s = 0;
#pragma unroll
    for (int i = 0; i < 32; i++) { v[i] = base[t * 32 + i]; s += v[i]; }
    tot[t] = s;
    __syncthreads();
    if (t == 0) {
        int acc = 0;
        for (int i = 0; i < 256; i++) { int x = tot[i]; tot[i] = acc; acc += x; }
    }
    __syncthreads();
    int ex = tot[t];
#pragma unroll
    for (int i = 0; i < 32; i++) { int x = v[i]; base[t * 32 + i] = ex; ex += x; }
}

// ---------------- 2c) parallel stable scatter ----------------
__global__ void k_scatter_par() {
    __shared__ int whist[4][TT];
    int b  = blockIdx.x / NCH;
    int ch = blockIdx.x % NCH;
    int t  = threadIdx.x;
    int lane = t & 31, w = t >> 5;
    ((int*)whist)[t] = 0;
    ((int*)whist)[t + 128] = 0;
    int key = g_tkid[b * NN + ch * CHSZ + t];
    __syncthreads();
    unsigned mask = __match_any_sync(0xffffffffu, key);
    int wrank = __popc(mask & ((1u << lane) - 1u));
    if (lane == (__ffs(mask) - 1))
        whist[w][key] = __popc(mask);
    __syncthreads();
    int off = 0;
#pragma unroll
    for (int w2 = 0; w2 < 3; w2++)
        if (w2 < w) off += whist[w2][key];
    int pos = g_hist[(b * TT + key) * NCH + ch] + off + wrank;
    g_sortidx[b * NN + pos] = ch * CHSZ + t;
}

// ---------------- 3) tensor-core attention, flash-chunked (R13 config) ----------------
#define AST 40
#define SM_Q_HI 0
#define SM_Q_LO (128 * AST)
#define SM_K_HI (2 * 128 * AST)
#define SM_K_LO (3 * 128 * AST)
#define SM_VF   (4 * 128 * AST)
#define SM_TOK  (5 * 128 * AST)
#define SMEM_ATT_BYTES (5 * 128 * AST * 2 + 128 * 4)

__global__ void __launch_bounds__(256, 3)
k_attn_mma(const float* __restrict__ qkv, const float* __restrict__ logit_scale) {
    __nv_bfloat16* sm = (__nv_bfloat16*)dynsm;
    __nv_bfloat16* Qh = sm + SM_Q_HI;
    __nv_bfloat16* Ql = sm + SM_Q_LO;
    __nv_bfloat16* Kh = sm + SM_K_HI;
    __nv_bfloat16* Kl = sm + SM_K_LO;
    __half*        Vf = (__half*)(sm + SM_VF);
    int* toks = (int*)(sm + SM_TOK);

    int h = blockIdx.x, g = blockIdx.y, b = blockIdx.z;
    int tid = threadIdx.x, lane = tid & 31, warp = tid >> 5;

    // ---- stage sorted token ids ----
    if (tid < GS) toks[tid] = g_sortidx[b * NN + g * GS + tid];
    __syncthreads();

    // ---- wavefront-minimal gather ----
    {
        const float* qb = qkv + (size_t)b * NN * C3 + h * DD;
        int rsub  = tid & 7;
        int rbase = tid >> 3;                       // 0..31
#pragma unroll
        for (int tsel = 0; tsel < 3; tsel++) {
            int rw[4];
            const float4* ap[4];
#pragma unroll
            for (int i2 = 0; i2 < 4; i2++) {
                rw[i2] = i2 * 32 + rbase;
                ap[i2] = (const float4*)(qb + (size_t)toks[rw[i2]] * C3 + tsel * CC + rsub * 4);
            }
#pragma unroll
            for (int i2 = 0; i2 < 4; i2++) {
                float4 x = *ap[i2];
                int row = rw[i2];
                if (tsel < 2) {
                    __nv_bfloat162 h01 = __floats2bfloat162_rn(x.x, x.y);
                    __nv_bfloat162 h23 = __floats2bfloat162_rn(x.z, x.w);
                    float2 f01 = __bfloat1622float2(h01);
                    float2 f23 = __bfloat1622float2(h23);
                    __nv_bfloat162 l01 = __floats2bfloat162_rn(x.x - f01.x, x.y - f01.y);
                    __nv_bfloat162 l23 = __floats2bfloat162_rn(x.z - f23.x, x.w - f23.y);
                    __nv_bfloat16* dh = (tsel == 0 ? Qh : Kh) + row * AST + rsub * 4;
                    __nv_bfloat16* dl = (tsel == 0 ? Ql : Kl) + row * AST + rsub * 4;
                    *(uint2*)dh = make_uint2(*(uint32_t*)&h01, *(uint32_t*)&h23);
                    *(uint2*)dl = make_uint2(*(uint32_t*)&l01, *(uint32_t*)&l23);
                } else {
                    __half2 p01 = __floats2half2_rn(x.x, x.y);
                    __half2 p23 = __floats2half2_rn(x.z, x.w);
                    *(uint2*)(Vf + row * AST + rsub * 4) =
                        make_uint2(*(uint32_t*)&p01, *(uint32_t*)&p23);
                }
            }
        }
    }
    // fold softmax scale and log2(e): p = exp2(s*sc2 - M2)
    float sc2 = __expf(fminf(logit_scale[0], 4.605170185988091f)) * 1.44269504088896f;
    __syncthreads();

    int m0 = warp * 16;
    int l16 = lane & 15;

    uint32_t qh[2][4];
#pragma unroll
    for (int ks = 0; ks < 2; ks++)
        ldm_x4(qh[ks], smem_u32(Qh + (m0 + l16) * AST + ks * 16 + (lane >> 4) * 8));

    float o[4][4];
#pragma unroll
    for (int nf = 0; nf < 4; nf++)
#pragma unroll
        for (int r = 0; r < 4; r++) o[nf][r] = 0.0f;
    float m01 = -1e30f, m23 = -1e30f, l01 = 0.0f, l23 = 0.0f;

#pragma unroll
    for (int chnk = 0; chnk < 2; chnk++) {
        int c0 = chnk * 64;
        uint32_t ql[2][4];
#pragma unroll
        for (int ks = 0; ks < 2; ks++)
            ldm_x4(ql[ks], smem_u32(Ql + (m0 + l16) * AST + ks * 16 + (lane >> 4) * 8));

        float s[8][4];
#pragma unroll
        for (int nf = 0; nf < 8; nf++)
#pragma unroll
            for (int r = 0; r < 4; r++) s[nf][r] = 0.0f;

#pragma unroll
        for (int p2 = 0; p2 < 4; p2++) {
            int j0 = c0 + p2 * 16;
#pragma unroll
            for (int ks = 0; ks < 2; ks++) {
                uint32_t kb[4], kl4[4];
                int krow = j0 + ((lane >> 4) << 3) + (lane & 7);
                int kcol = ks * 16 + ((lane >> 3) & 1) * 8;
                ldm_x4(kb,  smem_u32(Kh + krow * AST + kcol));
                ldm_x4(kl4, smem_u32(Kl + krow * AST + kcol));
                mma_bf16(s[2 * p2],     qh[ks], kb[0],  kb[1]);
                mma_bf16(s[2 * p2],     qh[ks], kl4[0], kl4[1]);
                mma_bf16(s[2 * p2],     ql[ks], kb[0],  kb[1]);
                mma_bf16(s[2 * p2 + 1], qh[ks], kb[2],  kb[3]);
                mma_bf16(s[2 * p2 + 1], qh[ks], kl4[2], kl4[3]);
                mma_bf16(s[2 * p2 + 1], ql[ks], kb[2],  kb[3]);
            }
        }

        // scale fold + chunk row-max (quad shfl)
        float cm01 = -1e30f, cm23 = -1e30f;
#pragma unroll
        for (int nf = 0; nf < 8; nf++) {
#pragma unroll
            for (int r = 0; r < 4; r++) s[nf][r] *= sc2;
            cm01 = fmaxf(cm01, fmaxf(s[nf][0], s[nf][1]));
            cm23 = fmaxf(cm23, fmaxf(s[nf][2], s[nf][3]));
        }
        cm01 = fmaxf(cm01, __shfl_xor_sync(0xffffffffu, cm01, 1));
        cm01 = fmaxf(cm01, __shfl_xor_sync(0xffffffffu, cm01, 2));
        cm23 = fmaxf(cm23, __shfl_xor_sync(0xffffffffu, cm23, 1));
        cm23 = fmaxf(cm23, __shfl_xor_sync(0xffffffffu, cm23, 2));

        // online update
        float nm01 = fmaxf(m01, cm01), nm23 = fmaxf(m23, cm23);
        float cor01 = exp2f(m01 - nm01), cor23 = exp2f(m23 - nm23);
        m01 = nm01; m23 = nm23;
#pragma unroll
        for (int nf = 0; nf < 4; nf++) {
            o[nf][0] *= cor01; o[nf][1] *= cor01;
            o[nf][2] *= cor23; o[nf][3] *= cor23;
        }

        float sum01 = 0.0f, sum23 = 0.0f;
#pragma unroll
        for (int nf = 0; nf < 8; nf++) {
            float e0 = exp2f(s[nf][0] - m01);
            float e1 = exp2f(s[nf][1] - m01);
            float e2 = exp2f(s[nf][2] - m23);
            float e3 = exp2f(s[nf][3] - m23);
            s[nf][0] = e0; s[nf][1] = e1; s[nf][2] = e2; s[nf][3] = e3;
            sum01 += e0 + e1;
            sum23 += e2 + e3;
        }
        sum01 += __shfl_xor_sync(0xffffffffu, sum01, 1);
        sum01 += __shfl_xor_sync(0xffffffffu, sum01, 2);
        sum23 += __shfl_xor_sync(0xffffffffu, sum23, 1);
        sum23 += __shfl_xor_sync(0xffffffffu, sum23, 2);
        l01 = l01 * cor01 + sum01;
        l23 = l23 * cor23 + sum23;

        // PV over this chunk's 64 k-rows
#pragma unroll
        for (int kj = 0; kj < 4; kj++) {
            int f0 = 2 * kj, f1 = 2 * kj + 1;
            uint32_t ph[4];
            ph[0] = packh2(s[f0][0], s[f0][1]);
            ph[1] = packh2(s[f0][2], s[f0][3]);
            ph[2] = packh2(s[f1][0], s[f1][1]);
            ph[3] = packh2(s[f1][2], s[f1][3]);
            int vrow = c0 + kj * 16 + l16;
#pragma unroll
            for (int dh2 = 0; dh2 < 2; dh2++) {
                uint32_t vf[4];
                ldm_x4_t(vf, smem_u32(Vf + vrow * AST + dh2 * 16 + ((lane >> 4) << 3)));
                mma_f16(o[2 * dh2],     ph, vf[0], vf[1]);
                mma_f16(o[2 * dh2 + 1], ph, vf[2], vf[3]);
            }
        }
    }

    // ---- epilogue: normalize, fp16, scatter to original token rows ----
    float inv0 = 1.0f / l01, inv1 = 1.0f / l23;
    int r0 = m0 + (lane >> 2);
    int tok0 = toks[r0], tok1 = toks[r0 + 8];
    size_t ob0 = (size_t)(b * NN + tok0) * CC + h * DD + (lane & 3) * 2;
    size_t ob1 = (size_t)(b * NN + tok1) * CC + h * DD + (lane & 3) * 2;
#pragma unroll
    for (int nf = 0; nf < 4; nf++) {
        *(__half2*)(g_y + ob0 + nf * 8) = __floats2half2_rn(o[nf][0] * inv0, o[nf][1] * inv0);
        *(__half2*)(g_y + ob1 + nf * 8) = __floats2half2_rn(o[nf][2] * inv1, o[nf][3] * inv1);
    }
}

// ---------------- 4) projection v3: BM=64, 3-stage cp.async, 3 CTAs/SM ----------------
// out[65536,256] = y(fp16) @ W(fp16)^T + bias. BM=64, BN=128, BK=32.
// 8 warps as 4(m) x 2(n): warp tile 16 x 64. Accums 32 regs -> ~70 total.
#define PST   40
#define P_ASZ (64 * PST)
#define P_BSZ (128 * PST)
#define PSTG3 (P_ASZ + P_BSZ)
#define SMEM_PROJ_BYTES (3 * PSTG3 * 2)

__global__ void __launch_bounds__(256, 3)
k_proj3(const float* __restrict__ bias, float* __restrict__ out) {
    __half* sm = (__half*)dynsm;

    int tid  = threadIdx.x;
    int lane = tid & 31;
    int warp = tid >> 5;
    int row0 = blockIdx.x * 64;
    int col0 = blockIdx.y * 128;
    int m_off = (warp & 3) * 16;
    int n_off = (warp >> 2) * 64;
    int l16 = lane & 15;

    int rA = tid >> 2;                 // 0..63
    int qA = (tid & 3) * 8;            // 8-elem (16B) unit within BK=32

    const __half* gA = g_y + (size_t)row0 * CC;
    const __half* gB = g_w + (size_t)col0 * CC;

    auto load_stage = [&](int st, int k0) {
        __half* Af = sm + st * PSTG3;
        __half* Bf = Af + P_ASZ;
        cp16(Af + rA * PST + qA,        gA + (size_t)rA * CC + k0 + qA);
        cp16(Bf + rA * PST + qA,        gB + (size_t)rA * CC + k0 + qA);
        cp16(Bf + (64 + rA) * PST + qA, gB + (size_t)(64 + rA) * CC + k0 + qA);
        CP_COMMIT();
    };

    float c[8][4];
#pragma unroll
    for (int nf = 0; nf < 8; nf++)
#pragma unroll
        for (int r = 0; r < 4; r++) c[nf][r] = 0.0f;

    load_stage(0, 0);
    load_stage(1, 32);

    for (int kt = 0; kt < 8; kt++) {
        if (kt + 2 < 8) {
            load_stage((kt + 2) % 3, (kt + 2) * 32);
            CP_WAIT(2);
        } else if (kt + 1 < 8) {
            CP_WAIT(1);
        } else {
            CP_WAIT(0);
        }
        __syncthreads();

        __half* Af = sm + (kt % 3) * PSTG3;
        __half* Bf = Af + P_ASZ;

#pragma unroll
        for (int kk = 0; kk < 32; kk += 16) {
            uint32_t bh[8][2];
#pragma unroll
            for (int np = 0; np < 4; np++) {
                uint32_t t4[4];
                int brow = n_off + np * 16 + ((lane >> 4) << 3) + (lane & 7);
                int bcol = kk + ((lane >> 3) & 1) * 8;
                ldm_x4(t4, smem_u32(Bf + brow * PST + bcol));
                bh[2 * np][0] = t4[0]; bh[2 * np][1] = t4[1];
                bh[2 * np + 1][0] = t4[2]; bh[2 * np + 1][1] = t4[3];
            }
            uint32_t af[4];
            int arow = m_off + l16;
            ldm_x4(af, smem_u32(Af + arow * PST + kk + (lane >> 4) * 8));
#pragma unroll
            for (int nf = 0; nf < 8; nf++)
                mma_f16(c[nf], af, bh[nf][0], bh[nf][1]);
        }
        __syncthreads();
    }

#pragma unroll
    for (int nf = 0; nf < 8; nf++) {
        int rg = row0 + m_off + (lane >> 2);
        int cg = col0 + n_off + nf * 8 + (lane & 3) * 2;
        float b0 = bias[cg], b1 = bias[cg + 1];
        float2* o0 = (float2*)(out + (size_t)rg * CC + cg);
        float2* o1 = (float2*)(out + (size_t)(rg + 8) * CC + cg);
        *o0 = make_float2(c[nf][0] + b0, c[nf][1] + b1);
        *o1 = make_float2(c[nf][2] + b0, c[nf][3] + b1);
    }
}

// ---------------- launch ----------------
extern "C" void kernel_launch(void* const* d_in, const int* in_sizes, int n_in,
                              void* d_out, int out_size) {
    const float* qkv         = (const float*)d_in[0];
    const float* sim         = (const float*)d_in[1];
    const float* proj_w      = (const float*)d_in[2];
    const float* proj_b      = (const float*)d_in[3];
    const float* logit_scale = (const float*)d_in[4];
    float* out = (float*)d_out;

    k_argmax_hist<<<BB * NCH, CHSZ>>>(sim, proj_w);
    k_scan<<<BB, 256>>>();
    k_scatter_par<<<BB * NCH, CHSZ>>>();

    // h fastest: 8 sibling head-blocks of one (b,g) co-run and share token rows in L2
    cudaFuncSetAttribute(k_attn_mma, cudaFuncAttributeMaxDynamicSharedMemorySize, SMEM_ATT_BYTES);
    k_attn_mma<<<dim3(HH, NG, BB), 256, SMEM_ATT_BYTES>>>(qkv, logit_scale);

    cudaFuncSetAttribute(k_proj3, cudaFuncAttributeMaxDynamicSharedMemorySize, SMEM_PROJ_BYTES);
    k_proj3<<<dim3((BB * NN) / 64, CC / 128), 256, SMEM_PROJ_BYTES>>>(proj_b, out);
}

// round 16
// speedup vs baseline: 1.1282x; 1.0002x over previous
#include <cuda_runtime.h>
#include <cuda_bf16.h>
#include <cuda_fp16.h>
#include <math.h>
#include <stdint.h>

// Problem constants (fixed by the benchmark shapes)
#define BB   4
#define NN   16384
#define CC   256
#define C3   768
#define TT   64
#define HH   8
#define DD   32
#define GS   128
#define NG   128
#define NCH  128
#define CHSZ 128

// -------- scratch (device globals) --------
__device__ int   g_tkid[BB * NN];
__device__ int   g_sortidx[BB * NN];
__device__ int   g_hist[BB * TT * NCH];
__device__ __half g_y[(size_t)BB * NN * CC];     // attention out, single fp16 plane
__device__ __half g_w[CC * CC];                  // W fp16 (1-term)

// ---------------- PTX helpers ----------------
__device__ __forceinline__ uint32_t smem_u32(const void* p) {
    return (uint32_t)__cvta_generic_to_shared(p);
}
__device__ __forceinline__ void ldm_x4(uint32_t* r, uint32_t a) {
    asm volatile("ldmatrix.sync.aligned.m8n8.x4.shared.b16 {%0,%1,%2,%3},[%4];"
                 : "=r"(r[0]), "=r"(r[1]), "=r"(r[2]), "=r"(r[3]) : "r"(a));
}
__device__ __forceinline__ void ldm_x4_t(uint32_t* r, uint32_t a) {
    asm volatile("ldmatrix.sync.aligned.m8n8.x4.trans.shared.b16 {%0,%1,%2,%3},[%4];"
                 : "=r"(r[0]), "=r"(r[1]), "=r"(r[2]), "=r"(r[3]) : "r"(a));
}
__device__ __forceinline__ void mma_bf16(float* c, const uint32_t* a, uint32_t b0, uint32_t b1) {
    asm volatile(
        "mma.sync.aligned.m16n8k16.row.col.f32.bf16.bf16.f32 "
        "{%0,%1,%2,%3},{%4,%5,%6,%7},{%8,%9},{%0,%1,%2,%3};"
        : "+f"(c[0]), "+f"(c[1]), "+f"(c[2]), "+f"(c[3])
        : "r"(a[0]), "r"(a[1]), "r"(a[2]), "r"(a[3]), "r"(b0), "r"(b1));
}
__device__ __forceinline__ void mma_f16(float* c, const uint32_t* a, uint32_t b0, uint32_t b1) {
    asm volatile(
        "mma.sync.aligned.m16n8k16.row.col.f32.f16.f16.f32 "
        "{%0,%1,%2,%3},{%4,%5,%6,%7},{%8,%9},{%0,%1,%2,%3};"
        : "+f"(c[0]), "+f"(c[1]), "+f"(c[2]), "+f"(c[3])
        : "r"(a[0]), "r"(a[1]), "r"(a[2]), "r"(a[3]), "r"(b0), "r"(b1));
}
__device__ __forceinline__ uint32_t packh2(float x, float y) {
    __half2 t = __floats2half2_rn(x, y);
    return *(uint32_t*)&t;
}
__device__ __forceinline__ void cp16(void* smem_dst, const void* gsrc) {
    asm volatile("cp.async.cg.shared.global [%0], [%1], 16;"
                 :: "r"(smem_u32(smem_dst)), "l"(gsrc));
}
#define CP_COMMIT()  asm volatile("cp.async.commit_group;")
#define CP_WAIT(N)   asm volatile("cp.async.wait_group %0;" :: "n"(N))

extern __shared__ __align__(16) char dynsm[];

// ---------------- 1+2a) fused argmax + histogram + W fp16 convert ----------------
__global__ void k_argmax_hist(const float* __restrict__ sim, const float* __restrict__ W) {
    __shared__ int h[TT];
    int b  = blockIdx.x / NCH;
    int ch = blockIdx.x % NCH;
    int t  = threadIdx.x;
    {
        int wi = blockIdx.x * CHSZ + t;
        g_w[wi] = __float2half_rn(W[wi]);
    }
    if (t < TT) h[t] = 0;
    int idx = b * NN + ch * CHSZ + t;
    const float4* p = (const float4*)(sim + (size_t)idx * TT);
    float best = -3.402823466e38f;
    int bi = 0;
#pragma unroll
    for (int i = 0; i < 16; i++) {
        float4 v = p[i];
        if (v.x > best) { best = v.x; bi = 4 * i + 0; }
        if (v.y > best) { best = v.y; bi = 4 * i + 1; }
        if (v.z > best) { best = v.z; bi = 4 * i + 2; }
        if (v.w > best) { best = v.w; bi = 4 * i + 3; }
    }
    g_tkid[idx] = bi;
    __syncthreads();
    atomicAdd(&h[bi], 1);
    __syncthreads();
    if (t < TT)
        g_hist[(b * TT + t) * NCH + ch] = h[t];
}

// ---------------- 2b) exclusive scan (parallel: shfl warp-scan) ----------------
__global__ void k_scan() {
    __shared__ int wsum[8];
    int b = blockIdx.x;
    int* base = g_hist + b * TT * NCH;
    int t = threadIdx.x, lane = t & 31, w = t >> 5;
    int v[32];
    int s = 0;
#pragma unroll
    for (int i = 0; i < 32; i++) { v[i] = base[t * 32 + i]; s += v[i]; }
    int inc = s;
#pragma unroll
    for (int d = 1; d < 32; d <<= 1) {
        int x = __shfl_up_sync(0xffffffffu, inc, d);
        if (lane >= d) inc += x;
    }
    if (lane == 31) wsum[w] = inc;
    __syncthreads();
    int off = 0;
#pragma unroll
    for (int w2 = 0; w2 < 8; w2++)
        if (w2 < w) off += wsum[w2];
    int ex = off + inc - s;
#pragma unroll
    for (int i = 0; i < 32; i++) { int x = v[i]; base[t * 32 + i] = ex; ex += x; }
}

// ---------------- 2c) parallel stable scatter ----------------
__global__ void k_scatter_par() {
    __shared__ int whist[4][TT];
    int b  = blockIdx.x / NCH;
    int ch = blockIdx.x % NCH;
    int t  = threadIdx.x;
    int lane = t & 31, w = t >> 5;
    ((int*)whist)[t] = 0;
    ((int*)whist)[t + 128] = 0;
    int key = g_tkid[b * NN + ch * CHSZ + t];
    __syncthreads();
    unsigned mask = __match_any_sync(0xffffffffu, key);
    int wrank = __popc(mask & ((1u << lane) - 1u));
    if (lane == (__ffs(mask) - 1))
        whist[w][key] = __popc(mask);
    __syncthreads();
    int off = 0;
#pragma unroll
    for (int w2 = 0; w2 < 3; w2++)
        if (w2 < w) off += whist[w2][key];
    int pos = g_hist[(b * TT + key) * NCH + ch] + off + wrank;
    g_sortidx[b * NN + pos] = ch * CHSZ + t;
}

// ---------------- 3) tensor-core attention, flash-chunked (R13 config) ----------------
#define AST 40
#define SM_Q_HI 0
#define SM_Q_LO (128 * AST)
#define SM_K_HI (2 * 128 * AST)
#define SM_K_LO (3 * 128 * AST)
#define SM_VF   (4 * 128 * AST)
#define SM_TOK  (5 * 128 * AST)
#define SMEM_ATT_BYTES (5 * 128 * AST * 2 + 128 * 4)

__global__ void __launch_bounds__(256, 3)
k_attn_mma(const float* __restrict__ qkv, const float* __restrict__ logit_scale) {
    __nv_bfloat16* sm = (__nv_bfloat16*)dynsm;
    __nv_bfloat16* Qh = sm + SM_Q_HI;
    __nv_bfloat16* Ql = sm + SM_Q_LO;
    __nv_bfloat16* Kh = sm + SM_K_HI;
    __nv_bfloat16* Kl = sm + SM_K_LO;
    __half*        Vf = (__half*)(sm + SM_VF);
    int* toks = (int*)(sm + SM_TOK);

    int h = blockIdx.x, g = blockIdx.y, b = blockIdx.z;
    int tid = threadIdx.x, lane = tid & 31, warp = tid >> 5;

    // ---- stage sorted token ids ----
    if (tid < GS) toks[tid] = g_sortidx[b * NN + g * GS + tid];
    __syncthreads();

    // ---- wavefront-minimal gather ----
    {
        const float* qb = qkv + (size_t)b * NN * C3 + h * DD;
        int rsub  = tid & 7;
        int rbase = tid >> 3;                       // 0..31
#pragma unroll
        for (int tsel = 0; tsel < 3; tsel++) {
            int rw[4];
            const float4* ap[4];
#pragma unroll
            for (int i2 = 0; i2 < 4; i2++) {
                rw[i2] = i2 * 32 + rbase;
                ap[i2] = (const float4*)(qb + (size_t)toks[rw[i2]] * C3 + tsel * CC + rsub * 4);
            }
#pragma unroll
            for (int i2 = 0; i2 < 4; i2++) {
                float4 x = *ap[i2];
                int row = rw[i2];
                if (tsel < 2) {
                    __nv_bfloat162 h01 = __floats2bfloat162_rn(x.x, x.y);
                    __nv_bfloat162 h23 = __floats2bfloat162_rn(x.z, x.w);
                    float2 f01 = __bfloat1622float2(h01);
                    float2 f23 = __bfloat1622float2(h23);
                    __nv_bfloat162 l01 = __floats2bfloat162_rn(x.x - f01.x, x.y - f01.y);
                    __nv_bfloat162 l23 = __floats2bfloat162_rn(x.z - f23.x, x.w - f23.y);
                    __nv_bfloat16* dh = (tsel == 0 ? Qh : Kh) + row * AST + rsub * 4;
                    __nv_bfloat16* dl = (tsel == 0 ? Ql : Kl) + row * AST + rsub * 4;
                    *(uint2*)dh = make_uint2(*(uint32_t*)&h01, *(uint32_t*)&h23);
                    *(uint2*)dl = make_uint2(*(uint32_t*)&l01, *(uint32_t*)&l23);
                } else {
                    __half2 p01 = __floats2half2_rn(x.x, x.y);
                    __half2 p23 = __floats2half2_rn(x.z, x.w);
                    *(uint2*)(Vf + row * AST + rsub * 4) =
                        make_uint2(*(uint32_t*)&p01, *(uint32_t*)&p23);
                }
            }
        }
    }
    // fold softmax scale and log2(e): p = exp2(s*sc2 - M2)
    float sc2 = __expf(fminf(logit_scale[0], 4.605170185988091f)) * 1.44269504088896f;
    __syncthreads();

    int m0 = warp * 16;
    int l16 = lane & 15;

    uint32_t qh[2][4];
#pragma unroll
    for (int ks = 0; ks < 2; ks++)
        ldm_x4(qh[ks], smem_u32(Qh + (m0 + l16) * AST + ks * 16 + (lane >> 4) * 8));

    float o[4][4];
#pragma unroll
    for (int nf = 0; nf < 4; nf++)
#pragma unroll
        for (int r = 0; r < 4; r++) o[nf][r] = 0.0f;
    float m01 = -1e30f, m23 = -1e30f, l01 = 0.0f, l23 = 0.0f;

#pragma unroll
    for (int chnk = 0; chnk < 2; chnk++) {
        int c0 = chnk * 64;
        uint32_t ql[2][4];
#pragma unroll
        for (int ks = 0; ks < 2; ks++)
            ldm_x4(ql[ks], smem_u32(Ql + (m0 + l16) * AST + ks * 16 + (lane >> 4) * 8));

        float s[8][4];
#pragma unroll
        for (int nf = 0; nf < 8; nf++)
#pragma unroll
            for (int r = 0; r < 4; r++) s[nf][r] = 0.0f;

#pragma unroll
        for (int p2 = 0; p2 < 4; p2++) {
            int j0 = c0 + p2 * 16;
#pragma unroll
            for (int ks = 0; ks < 2; ks++) {
                uint32_t kb[4], kl4[4];
                int krow = j0 + ((lane >> 4) << 3) + (lane & 7);
                int kcol = ks * 16 + ((lane >> 3) & 1) * 8;
                ldm_x4(kb,  smem_u32(Kh + krow * AST + kcol));
                ldm_x4(kl4, smem_u32(Kl + krow * AST + kcol));
                mma_bf16(s[2 * p2],     qh[ks], kb[0],  kb[1]);
                mma_bf16(s[2 * p2],     qh[ks], kl4[0], kl4[1]);
                mma_bf16(s[2 * p2],     ql[ks], kb[0],  kb[1]);
                mma_bf16(s[2 * p2 + 1], qh[ks], kb[2],  kb[3]);
                mma_bf16(s[2 * p2 + 1], qh[ks], kl4[2], kl4[3]);
                mma_bf16(s[2 * p2 + 1], ql[ks], kb[2],  kb[3]);
            }
        }

        // scale fold + chunk row-max (quad shfl)
        float cm01 = -1e30f, cm23 = -1e30f;
#pragma unroll
        for (int nf = 0; nf < 8; nf++) {
#pragma unroll
            for (int r = 0; r < 4; r++) s[nf][r] *= sc2;
            cm01 = fmaxf(cm01, fmaxf(s[nf][0], s[nf][1]));
            cm23 = fmaxf(cm23, fmaxf(s[nf][2], s[nf][3]));
        }
        cm01 = fmaxf(cm01, __shfl_xor_sync(0xffffffffu, cm01, 1));
        cm01 = fmaxf(cm01, __shfl_xor_sync(0xffffffffu, cm01, 2));
        cm23 = fmaxf(cm23, __shfl_xor_sync(0xffffffffu, cm23, 1));
        cm23 = fmaxf(cm23, __shfl_xor_sync(0xffffffffu, cm23, 2));

        // online update
        float nm01 = fmaxf(m01, cm01), nm23 = fmaxf(m23, cm23);
        float cor01 = exp2f(m01 - nm01), cor23 = exp2f(m23 - nm23);
        m01 = nm01; m23 = nm23;
#pragma unroll
        for (int nf = 0; nf < 4; nf++) {
            o[nf][0] *= cor01; o[nf][1] *= cor01;
            o[nf][2] *= cor23; o[nf][3] *= cor23;
        }

        float sum01 = 0.0f, sum23 = 0.0f;
#pragma unroll
        for (int nf = 0; nf < 8; nf++) {
            float e0 = exp2f(s[nf][0] - m01);
            float e1 = exp2f(s[nf][1] - m01);
            float e2 = exp2f(s[nf][2] - m23);
            float e3 = exp2f(s[nf][3] - m23);
            s[nf][0] = e0; s[nf][1] = e1; s[nf][2] = e2; s[nf][3] = e3;
            sum01 += e0 + e1;
            sum23 += e2 + e3;
        }
        sum01 += __shfl_xor_sync(0xffffffffu, sum01, 1);
        sum01 += __shfl_xor_sync(0xffffffffu, sum01, 2);
        sum23 += __shfl_xor_sync(0xffffffffu, sum23, 1);
        sum23 += __shfl_xor_sync(0xffffffffu, sum23, 2);
        l01 = l01 * cor01 + sum01;
        l23 = l23 * cor23 + sum23;

        // PV over this chunk's 64 k-rows
#pragma unroll
        for (int kj = 0; kj < 4; kj++) {
            int f0 = 2 * kj, f1 = 2 * kj + 1;
            uint32_t ph[4];
            ph[0] = packh2(s[f0][0], s[f0][1]);
            ph[1] = packh2(s[f0][2], s[f0][3]);
            ph[2] = packh2(s[f1][0], s[f1][1]);
            ph[3] = packh2(s[f1][2], s[f1][3]);
            int vrow = c0 + kj * 16 + l16;
#pragma unroll
            for (int dh2 = 0; dh2 < 2; dh2++) {
                uint32_t vf[4];
                ldm_x4_t(vf, smem_u32(Vf + vrow * AST + dh2 * 16 + ((lane >> 4) << 3)));
                mma_f16(o[2 * dh2],     ph, vf[0], vf[1]);
                mma_f16(o[2 * dh2 + 1], ph, vf[2], vf[3]);
            }
        }
    }

    // ---- epilogue: normalize, fp16, scatter to original token rows ----
    float inv0 = 1.0f / l01, inv1 = 1.0f / l23;
    int r0 = m0 + (lane >> 2);
    int tok0 = toks[r0], tok1 = toks[r0 + 8];
    size_t ob0 = (size_t)(b * NN + tok0) * CC + h * DD + (lane & 3) * 2;
    size_t ob1 = (size_t)(b * NN + tok1) * CC + h * DD + (lane & 3) * 2;
#pragma unroll
    for (int nf = 0; nf < 4; nf++) {
        *(__half2*)(g_y + ob0 + nf * 8) = __floats2half2_rn(o[nf][0] * inv0, o[nf][1] * inv0);
        *(__half2*)(g_y + ob1 + nf * 8) = __floats2half2_rn(o[nf][2] * inv1, o[nf][3] * inv1);
    }
}

// ---------------- 4) projection: fp16 1-term, BM=BN=128, BK=64, 2-stage ----------------
// 4 mainloop iterations (half the syncs of BK=32). PST2=72 (144B row, 16B-aligned).
#define PST2  72
#define PPL2  (128 * PST2)
#define PSTG2 (2 * PPL2)
#define SMEM_PROJ_BYTES (2 * PSTG2 * 2)

__global__ void __launch_bounds__(256)
k_proj2(const float* __restrict__ bias, float* __restrict__ out) {
    __half* sm = (__half*)dynsm;

    int tid  = threadIdx.x;
    int lane = tid & 31;
    int warp = tid >> 5;
    int row0 = blockIdx.x * 128;
    int col0 = blockIdx.y * 128;
    int m_off = (warp & 3) * 32;
    int n_off = (warp >> 2) * 64;
    int l16 = lane & 15;

    // per-stage loads: A,B each 128 rows x 64 cols; thread t: row t>>1,
    // 16B sub-chunks 4*(t&1)..4*(t&1)+3 (warp covers 16 full 128B rows).
    int rA  = tid >> 1;
    int sb0 = (tid & 1) * 4;

    const __half* gA = g_y + (size_t)row0 * CC;
    const __half* gB = g_w + (size_t)col0 * CC;

    auto load_stage = [&](int st, int k0) {
        __half* Af = sm + st * PSTG2;
        __half* Bf = Af + PPL2;
#pragma unroll
        for (int j = 0; j < 4; j++) {
            int sub = sb0 + j;
            cp16(Af + rA * PST2 + sub * 8, gA + (size_t)rA * CC + k0 + sub * 8);
            cp16(Bf + rA * PST2 + sub * 8, gB + (size_t)rA * CC + k0 + sub * 8);
        }
        CP_COMMIT();
    };

    float c[2][8][4];
#pragma unroll
    for (int mf = 0; mf < 2; mf++)
#pragma unroll
        for (int nf = 0; nf < 8; nf++)
#pragma unroll
            for (int r = 0; r < 4; r++) c[mf][nf][r] = 0.0f;

    load_stage(0, 0);

    for (int kt = 0; kt < 4; kt++) {
        if (kt + 1 < 4) {
            load_stage((kt + 1) & 1, (kt + 1) * 64);
            CP_WAIT(1);
        } else {
            CP_WAIT(0);
        }
        __syncthreads();

        __half* Af = sm + (kt & 1) * PSTG2;
        __half* Bf = Af + PPL2;

#pragma unroll
        for (int kk = 0; kk < 64; kk += 16) {
            uint32_t bh[8][2];
#pragma unroll
            for (int np = 0; np < 4; np++) {
                uint32_t t4[4];
                int brow = n_off + np * 16 + ((lane >> 4) << 3) + (lane & 7);
                int bcol = kk + ((lane >> 3) & 1) * 8;
                ldm_x4(t4, smem_u32(Bf + brow * PST2 + bcol));
                bh[2 * np][0] = t4[0]; bh[2 * np][1] = t4[1];
                bh[2 * np + 1][0] = t4[2]; bh[2 * np + 1][1] = t4[3];
            }
#pragma unroll
            for (int mf = 0; mf < 2; mf++) {
                uint32_t af[4];
                int arow = m_off + mf * 16 + l16;
                ldm_x4(af, smem_u32(Af + arow * PST2 + kk + (lane >> 4) * 8));
#pragma unroll
                for (int nf = 0; nf < 8; nf++)
                    mma_f16(c[mf][nf], af, bh[nf][0], bh[nf][1]);
            }
        }
        __syncthreads();
    }

#pragma unroll
    for (int mf = 0; mf < 2; mf++) {
#pragma unroll
        for (int nf = 0; nf < 8; nf++) {
            int rg = row0 + m_off + mf * 16 + (lane >> 2);
            int cg = col0 + n_off + nf * 8 + (lane & 3) * 2;
            float b0 = bias[cg], b1 = bias[cg + 1];
            float2* o0 = (float2*)(out + (size_t)rg * CC + cg);
            float2* o1 = (float2*)(out + (size_t)(rg + 8) * CC + cg);
            *o0 = make_float2(c[mf][nf][0] + b0, c[mf][nf][1] + b1);
            *o1 = make_float2(c[mf][nf][2] + b0, c[mf][nf][3] + b1);
        }
    }
}

// ---------------- launch ----------------
extern "C" void kernel_launch(void* const* d_in, const int* in_sizes, int n_in,
                              void* d_out, int out_size) {
    const float* qkv         = (const float*)d_in[0];
    const float* sim         = (const float*)d_in[1];
    const float* proj_w      = (const float*)d_in[2];
    const float* proj_b      = (const float*)d_in[3];
    const float* logit_scale = (const float*)d_in[4];
    float* out = (float*)d_out;

    k_argmax_hist<<<BB * NCH, CHSZ>>>(sim, proj_w);
    k_scan<<<BB, 256>>>();
    k_scatter_par<<<BB * NCH, CHSZ>>>();

    // h fastest: 8 sibling head-blocks of one (b,g) co-run and share token rows in L2
    cudaFuncSetAttribute(k_attn_mma, cudaFuncAttributeMaxDynamicSharedMemorySize, SMEM_ATT_BYTES);
    k_attn_mma<<<dim3(HH, NG, BB), 256, SMEM_ATT_BYTES>>>(qkv, logit_scale);

    cudaFuncSetAttribute(k_proj2, cudaFuncAttributeMaxDynamicSharedMemorySize, SMEM_PROJ_BYTES);
    k_proj2<<<dim3((BB * NN) / 128, CC / 128), 256, SMEM_PROJ_BYTES>>>(proj_b, out);
}

// round 17
// speedup vs baseline: 1.1775x; 1.0437x over previous
#include <cuda_runtime.h>
#include <cuda_bf16.h>
#include <cuda_fp16.h>
#include <math.h>
#include <stdint.h>

// Problem constants (fixed by the benchmark shapes)
#define BB   4
#define NN   16384
#define CC   256
#define C3   768
#define TT   64
#define HH   8
#define DD   32
#define GS   128
#define NG   128
#define NCH  128
#define CHSZ 128

// -------- scratch (device globals) --------
__device__ int   g_tkid[BB * NN];
__device__ int   g_sortidx[BB * NN];
__device__ int   g_hist[BB * TT * NCH];
__device__ __half g_y[(size_t)BB * NN * CC];     // attention out, single fp16 plane
__device__ __half g_w[CC * CC];                  // W fp16 (1-term)

// ---------------- PTX helpers ----------------
__device__ __forceinline__ uint32_t smem_u32(const void* p) {
    return (uint32_t)__cvta_generic_to_shared(p);
}
__device__ __forceinline__ void ldm_x4(uint32_t* r, uint32_t a) {
    asm volatile("ldmatrix.sync.aligned.m8n8.x4.shared.b16 {%0,%1,%2,%3},[%4];"
                 : "=r"(r[0]), "=r"(r[1]), "=r"(r[2]), "=r"(r[3]) : "r"(a));
}
__device__ __forceinline__ void ldm_x4_t(uint32_t* r, uint32_t a) {
    asm volatile("ldmatrix.sync.aligned.m8n8.x4.trans.shared.b16 {%0,%1,%2,%3},[%4];"
                 : "=r"(r[0]), "=r"(r[1]), "=r"(r[2]), "=r"(r[3]) : "r"(a));
}
__device__ __forceinline__ void mma_bf16(float* c, const uint32_t* a, uint32_t b0, uint32_t b1) {
    asm volatile(
        "mma.sync.aligned.m16n8k16.row.col.f32.bf16.bf16.f32 "
        "{%0,%1,%2,%3},{%4,%5,%6,%7},{%8,%9},{%0,%1,%2,%3};"
        : "+f"(c[0]), "+f"(c[1]), "+f"(c[2]), "+f"(c[3])
        : "r"(a[0]), "r"(a[1]), "r"(a[2]), "r"(a[3]), "r"(b0), "r"(b1));
}
__device__ __forceinline__ void mma_f16(float* c, const uint32_t* a, uint32_t b0, uint32_t b1) {
    asm volatile(
        "mma.sync.aligned.m16n8k16.row.col.f32.f16.f16.f32 "
        "{%0,%1,%2,%3},{%4,%5,%6,%7},{%8,%9},{%0,%1,%2,%3};"
        : "+f"(c[0]), "+f"(c[1]), "+f"(c[2]), "+f"(c[3])
        : "r"(a[0]), "r"(a[1]), "r"(a[2]), "r"(a[3]), "r"(b0), "r"(b1));
}
__device__ __forceinline__ uint32_t packh2(float x, float y) {
    __half2 t = __floats2half2_rn(x, y);
    return *(uint32_t*)&t;
}
__device__ __forceinline__ void cp16(void* smem_dst, const void* gsrc) {
    asm volatile("cp.async.cg.shared.global [%0], [%1], 16;"
                 :: "r"(smem_u32(smem_dst)), "l"(gsrc));
}
#define CP_COMMIT()  asm volatile("cp.async.commit_group;")
#define CP_WAIT(N)   asm volatile("cp.async.wait_group %0;" :: "n"(N))

extern __shared__ __align__(16) char dynsm[];

// ---------------- 1+2a) fused argmax + histogram + W fp16 convert ----------------
__global__ void k_argmax_hist(const float* __restrict__ sim, const float* __restrict__ W) {
    __shared__ int h[TT];
    int b  = blockIdx.x / NCH;
    int ch = blockIdx.x % NCH;
    int t  = threadIdx.x;
    {
        int wi = blockIdx.x * CHSZ + t;
        g_w[wi] = __float2half_rn(W[wi]);
    }
    if (t < TT) h[t] = 0;
    int idx = b * NN + ch * CHSZ + t;
    const float4* p = (const float4*)(sim + (size_t)idx * TT);
    float best = -3.402823466e38f;
    int bi = 0;
#pragma unroll
    for (int i = 0; i < 16; i++) {
        float4 v = p[i];
        if (v.x > best) { best = v.x; bi = 4 * i + 0; }
        if (v.y > best) { best = v.y; bi = 4 * i + 1; }
        if (v.z > best) { best = v.z; bi = 4 * i + 2; }
        if (v.w > best) { best = v.w; bi = 4 * i + 3; }
    }
    g_tkid[idx] = bi;
    __syncthreads();
    atomicAdd(&h[bi], 1);
    __syncthreads();
    if (t < TT)
        g_hist[(b * TT + t) * NCH + ch] = h[t];
}

// ---------------- 2b) exclusive scan (parallel: shfl warp-scan) ----------------
__global__ void k_scan() {
    __shared__ int wsum[8];
    int b = blockIdx.x;
    int* base = g_hist + b * TT * NCH;
    int t = threadIdx.x, lane = t & 31, w = t >> 5;
    int v[32];
    int s = 0;
#pragma unroll
    for (int i = 0; i < 32; i++) { v[i] = base[t * 32 + i]; s += v[i]; }
    int inc = s;
#pragma unroll
    for (int d = 1; d < 32; d <<= 1) {
        int x = __shfl_up_sync(0xffffffffu, inc, d);
        if (lane >= d) inc += x;
    }
    if (lane == 31) wsum[w] = inc;
    __syncthreads();
    int off = 0;
#pragma unroll
    for (int w2 = 0; w2 < 8; w2++)
        if (w2 < w) off += wsum[w2];
    int ex = off + inc - s;
#pragma unroll
    for (int i = 0; i < 32; i++) { int x = v[i]; base[t * 32 + i] = ex; ex += x; }
}

// ---------------- 2c) parallel stable scatter ----------------
__global__ void k_scatter_par() {
    __shared__ int whist[4][TT];
    int b  = blockIdx.x / NCH;
    int ch = blockIdx.x % NCH;
    int t  = threadIdx.x;
    int lane = t & 31, w = t >> 5;
    ((int*)whist)[t] = 0;
    ((int*)whist)[t + 128] = 0;
    int key = g_tkid[b * NN + ch * CHSZ + t];
    __syncthreads();
    unsigned mask = __match_any_sync(0xffffffffu, key);
    int wrank = __popc(mask & ((1u << lane) - 1u));
    if (lane == (__ffs(mask) - 1))
        whist[w][key] = __popc(mask);
    __syncthreads();
    int off = 0;
#pragma unroll
    for (int w2 = 0; w2 < 3; w2++)
        if (w2 < w) off += whist[w2][key];
    int pos = g_hist[(b * TT + key) * NCH + ch] + off + wrank;
    g_sortidx[b * NN + pos] = ch * CHSZ + t;
}

// ---------------- 3) tensor-core attention, flash-chunked (R13 config) ----------------
#define AST 40
#define SM_Q_HI 0
#define SM_Q_LO (128 * AST)
#define SM_K_HI (2 * 128 * AST)
#define SM_K_LO (3 * 128 * AST)
#define SM_VF   (4 * 128 * AST)
#define SM_TOK  (5 * 128 * AST)
#define SMEM_ATT_BYTES (5 * 128 * AST * 2 + 128 * 4)

__global__ void __launch_bounds__(256, 3)
k_attn_mma(const float* __restrict__ qkv, const float* __restrict__ logit_scale) {
    __nv_bfloat16* sm = (__nv_bfloat16*)dynsm;
    __nv_bfloat16* Qh = sm + SM_Q_HI;
    __nv_bfloat16* Ql = sm + SM_Q_LO;
    __nv_bfloat16* Kh = sm + SM_K_HI;
    __nv_bfloat16* Kl = sm + SM_K_LO;
    __half*        Vf = (__half*)(sm + SM_VF);
    int* toks = (int*)(sm + SM_TOK);

    int h = blockIdx.x, g = blockIdx.y, b = blockIdx.z;
    int tid = threadIdx.x, lane = tid & 31, warp = tid >> 5;

    // ---- stage sorted token ids ----
    if (tid < GS) toks[tid] = g_sortidx[b * NN + g * GS + tid];
    __syncthreads();

    // ---- wavefront-minimal gather: 8 lanes cover one 128B token-slice per LDG ----
    {
        const float* qb = qkv + (size_t)b * NN * C3 + h * DD;
        int rsub  = tid & 7;
        int rbase = tid >> 3;                       // 0..31
#pragma unroll
        for (int tsel = 0; tsel < 3; tsel++) {
            int rw[4];
            const float4* ap[4];
#pragma unroll
            for (int i2 = 0; i2 < 4; i2++) {
                rw[i2] = i2 * 32 + rbase;
                ap[i2] = (const float4*)(qb + (size_t)toks[rw[i2]] * C3 + tsel * CC + rsub * 4);
            }
#pragma unroll
            for (int i2 = 0; i2 < 4; i2++) {
                float4 x = *ap[i2];
                int row = rw[i2];
                if (tsel < 2) {
                    __nv_bfloat162 h01 = __floats2bfloat162_rn(x.x, x.y);
                    __nv_bfloat162 h23 = __floats2bfloat162_rn(x.z, x.w);
                    float2 f01 = __bfloat1622float2(h01);
                    float2 f23 = __bfloat1622float2(h23);
                    __nv_bfloat162 l01 = __floats2bfloat162_rn(x.x - f01.x, x.y - f01.y);
                    __nv_bfloat162 l23 = __floats2bfloat162_rn(x.z - f23.x, x.w - f23.y);
                    __nv_bfloat16* dh = (tsel == 0 ? Qh : Kh) + row * AST + rsub * 4;
                    __nv_bfloat16* dl = (tsel == 0 ? Ql : Kl) + row * AST + rsub * 4;
                    *(uint2*)dh = make_uint2(*(uint32_t*)&h01, *(uint32_t*)&h23);
                    *(uint2*)dl = make_uint2(*(uint32_t*)&l01, *(uint32_t*)&l23);
                } else {
                    __half2 p01 = __floats2half2_rn(x.x, x.y);
                    __half2 p23 = __floats2half2_rn(x.z, x.w);
                    *(uint2*)(Vf + row * AST + rsub * 4) =
                        make_uint2(*(uint32_t*)&p01, *(uint32_t*)&p23);
                }
            }
        }
    }
    // fold softmax scale and log2(e): p = exp2(s*sc2 - M2)
    float sc2 = __expf(fminf(logit_scale[0], 4.605170185988091f)) * 1.44269504088896f;
    __syncthreads();

    int m0 = warp * 16;
    int l16 = lane & 15;

    uint32_t qh[2][4];
#pragma unroll
    for (int ks = 0; ks < 2; ks++)
        ldm_x4(qh[ks], smem_u32(Qh + (m0 + l16) * AST + ks * 16 + (lane >> 4) * 8));

    float o[4][4];
#pragma unroll
    for (int nf = 0; nf < 4; nf++)
#pragma unroll
        for (int r = 0; r < 4; r++) o[nf][r] = 0.0f;
    float m01 = -1e30f, m23 = -1e30f, l01 = 0.0f, l23 = 0.0f;

#pragma unroll
    for (int chnk = 0; chnk < 2; chnk++) {
        int c0 = chnk * 64;
        uint32_t ql[2][4];
#pragma unroll
        for (int ks = 0; ks < 2; ks++)
            ldm_x4(ql[ks], smem_u32(Ql + (m0 + l16) * AST + ks * 16 + (lane >> 4) * 8));

        float s[8][4];
#pragma unroll
        for (int nf = 0; nf < 8; nf++)
#pragma unroll
            for (int r = 0; r < 4; r++) s[nf][r] = 0.0f;

#pragma unroll
        for (int p2 = 0; p2 < 4; p2++) {
            int j0 = c0 + p2 * 16;
#pragma unroll
            for (int ks = 0; ks < 2; ks++) {
                uint32_t kb[4], kl4[4];
                int krow = j0 + ((lane >> 4) << 3) + (lane & 7);
                int kcol = ks * 16 + ((lane >> 3) & 1) * 8;
                ldm_x4(kb,  smem_u32(Kh + krow * AST + kcol));
                ldm_x4(kl4, smem_u32(Kl + krow * AST + kcol));
                mma_bf16(s[2 * p2],     qh[ks], kb[0],  kb[1]);
                mma_bf16(s[2 * p2],     qh[ks], kl4[0], kl4[1]);
                mma_bf16(s[2 * p2],     ql[ks], kb[0],  kb[1]);
                mma_bf16(s[2 * p2 + 1], qh[ks], kb[2],  kb[3]);
                mma_bf16(s[2 * p2 + 1], qh[ks], kl4[2], kl4[3]);
                mma_bf16(s[2 * p2 + 1], ql[ks], kb[2],  kb[3]);
            }
        }

        // scale fold + chunk row-max (quad shfl)
        float cm01 = -1e30f, cm23 = -1e30f;
#pragma unroll
        for (int nf = 0; nf < 8; nf++) {
#pragma unroll
            for (int r = 0; r < 4; r++) s[nf][r] *= sc2;
            cm01 = fmaxf(cm01, fmaxf(s[nf][0], s[nf][1]));
            cm23 = fmaxf(cm23, fmaxf(s[nf][2], s[nf][3]));
        }
        cm01 = fmaxf(cm01, __shfl_xor_sync(0xffffffffu, cm01, 1));
        cm01 = fmaxf(cm01, __shfl_xor_sync(0xffffffffu, cm01, 2));
        cm23 = fmaxf(cm23, __shfl_xor_sync(0xffffffffu, cm23, 1));
        cm23 = fmaxf(cm23, __shfl_xor_sync(0xffffffffu, cm23, 2));

        // online update
        float nm01 = fmaxf(m01, cm01), nm23 = fmaxf(m23, cm23);
        float cor01 = exp2f(m01 - nm01), cor23 = exp2f(m23 - nm23);
        m01 = nm01; m23 = nm23;
#pragma unroll
        for (int nf = 0; nf < 4; nf++) {
            o[nf][0] *= cor01; o[nf][1] *= cor01;
            o[nf][2] *= cor23; o[nf][3] *= cor23;
        }

        float sum01 = 0.0f, sum23 = 0.0f;
#pragma unroll
        for (int nf = 0; nf < 8; nf++) {
            float e0 = exp2f(s[nf][0] - m01);
            float e1 = exp2f(s[nf][1] - m01);
            float e2 = exp2f(s[nf][2] - m23);
            float e3 = exp2f(s[nf][3] - m23);
            s[nf][0] = e0; s[nf][1] = e1; s[nf][2] = e2; s[nf][3] = e3;
            sum01 += e0 + e1;
            sum23 += e2 + e3;
        }
        sum01 += __shfl_xor_sync(0xffffffffu, sum01, 1);
        sum01 += __shfl_xor_sync(0xffffffffu, sum01, 2);
        sum23 += __shfl_xor_sync(0xffffffffu, sum23, 1);
        sum23 += __shfl_xor_sync(0xffffffffu, sum23, 2);
        l01 = l01 * cor01 + sum01;
        l23 = l23 * cor23 + sum23;

        // PV over this chunk's 64 k-rows
#pragma unroll
        for (int kj = 0; kj < 4; kj++) {
            int f0 = 2 * kj, f1 = 2 * kj + 1;
            uint32_t ph[4];
            ph[0] = packh2(s[f0][0], s[f0][1]);
            ph[1] = packh2(s[f0][2], s[f0][3]);
            ph[2] = packh2(s[f1][0], s[f1][1]);
            ph[3] = packh2(s[f1][2], s[f1][3]);
            int vrow = c0 + kj * 16 + l16;
#pragma unroll
            for (int dh2 = 0; dh2 < 2; dh2++) {
                uint32_t vf[4];
                ldm_x4_t(vf, smem_u32(Vf + vrow * AST + dh2 * 16 + ((lane >> 4) << 3)));
                mma_f16(o[2 * dh2],     ph, vf[0], vf[1]);
                mma_f16(o[2 * dh2 + 1], ph, vf[2], vf[3]);
            }
        }
    }

    // ---- epilogue: normalize, fp16, scatter to original token rows ----
    float inv0 = 1.0f / l01, inv1 = 1.0f / l23;
    int r0 = m0 + (lane >> 2);
    int tok0 = toks[r0], tok1 = toks[r0 + 8];
    size_t ob0 = (size_t)(b * NN + tok0) * CC + h * DD + (lane & 3) * 2;
    size_t ob1 = (size_t)(b * NN + tok1) * CC + h * DD + (lane & 3) * 2;
#pragma unroll
    for (int nf = 0; nf < 4; nf++) {
        *(__half2*)(g_y + ob0 + nf * 8) = __floats2half2_rn(o[nf][0] * inv0, o[nf][1] * inv0);
        *(__half2*)(g_y + ob1 + nf * 8) = __floats2half2_rn(o[nf][2] * inv1, o[nf][3] * inv1);
    }
}

// ---------------- 4) projection: fp16 1-term MMA, BK=32, PST=40, 2-stage (R13) ----------------
#define PST  40
#define PPL  (128 * PST)
#define PSTG (2 * PPL)
#define SMEM_PROJ_BYTES (2 * PSTG * 2)

__global__ void __launch_bounds__(256)
k_proj2(const float* __restrict__ bias, float* __restrict__ out) {
    __half* sm = (__half*)dynsm;

    int tid  = threadIdx.x;
    int lane = tid & 31;
    int warp = tid >> 5;
    int row0 = blockIdx.x * 128;
    int col0 = blockIdx.y * 128;
    int m_off = (warp & 3) * 32;
    int n_off = (warp >> 2) * 64;
    int l16 = lane & 15;

    int c0 = tid * 2;
    int rA0 = c0 >> 2, qA0 = (c0 & 3) * 8;
    int rA1 = (c0 + 1) >> 2, qA1 = ((c0 + 1) & 3) * 8;

    const __half* gA = g_y + (size_t)row0 * CC;
    const __half* gB = g_w + (size_t)col0 * CC;

    auto load_stage = [&](int st, int k0) {
        __half* Af = sm + st * PSTG;
        __half* Bf = Af + PPL;
        cp16(Af + rA0 * PST + qA0, gA + (size_t)rA0 * CC + k0 + qA0);
        cp16(Af + rA1 * PST + qA1, gA + (size_t)rA1 * CC + k0 + qA1);
        cp16(Bf + rA0 * PST + qA0, gB + (size_t)rA0 * CC + k0 + qA0);
        cp16(Bf + rA1 * PST + qA1, gB + (size_t)rA1 * CC + k0 + qA1);
        CP_COMMIT();
    };

    float c[2][8][4];
#pragma unroll
    for (int mf = 0; mf < 2; mf++)
#pragma unroll
        for (int nf = 0; nf < 8; nf++)
#pragma unroll
            for (int r = 0; r < 4; r++) c[mf][nf][r] = 0.0f;

    load_stage(0, 0);

    for (int kt = 0; kt < 8; kt++) {
        if (kt + 1 < 8) {
            load_stage((kt + 1) & 1, (kt + 1) * 32);
            CP_WAIT(1);
        } else {
            CP_WAIT(0);
        }
        __syncthreads();

        __half* Af = sm + (kt & 1) * PSTG;
        __half* Bf = Af + PPL;

#pragma unroll
        for (int kk = 0; kk < 32; kk += 16) {
            uint32_t bh[8][2];
#pragma unroll
            for (int np = 0; np < 4; np++) {
                uint32_t t4[4];
                int brow = n_off + np * 16 + ((lane >> 4) << 3) + (lane & 7);
                int bcol = kk + ((lane >> 3) & 1) * 8;
                ldm_x4(t4, smem_u32(Bf + brow * PST + bcol));
                bh[2 * np][0] = t4[0]; bh[2 * np][1] = t4[1];
                bh[2 * np + 1][0] = t4[2]; bh[2 * np + 1][1] = t4[3];
            }
#pragma unroll
            for (int mf = 0; mf < 2; mf++) {
                uint32_t af[4];
                int arow = m_off + mf * 16 + l16;
                ldm_x4(af, smem_u32(Af + arow * PST + kk + (lane >> 4) * 8));
#pragma unroll
                for (int nf = 0; nf < 8; nf++)
                    mma_f16(c[mf][nf], af, bh[nf][0], bh[nf][1]);
            }
        }
        __syncthreads();
    }

#pragma unroll
    for (int mf = 0; mf < 2; mf++) {
#pragma unroll
        for (int nf = 0; nf < 8; nf++) {
            int rg = row0 + m_off + mf * 16 + (lane >> 2);
            int cg = col0 + n_off + nf * 8 + (lane & 3) * 2;
            float b0 = bias[cg], b1 = bias[cg + 1];
            float2* o0 = (float2*)(out + (size_t)rg * CC + cg);
            float2* o1 = (float2*)(out + (size_t)(rg + 8) * CC + cg);
            *o0 = make_float2(c[mf][nf][0] + b0, c[mf][nf][1] + b1);
            *o1 = make_float2(c[mf][nf][2] + b0, c[mf][nf][3] + b1);
        }
    }
}

// ---------------- launch ----------------
extern "C" void kernel_launch(void* const* d_in, const int* in_sizes, int n_in,
                              void* d_out, int out_size) {
    const float* qkv         = (const float*)d_in[0];
    const float* sim         = (const float*)d_in[1];
    const float* proj_w      = (const float*)d_in[2];
    const float* proj_b      = (const float*)d_in[3];
    const float* logit_scale = (const float*)d_in[4];
    float* out = (float*)d_out;

    k_argmax_hist<<<BB * NCH, CHSZ>>>(sim, proj_w);
    k_scan<<<BB, 256>>>();
    k_scatter_par<<<BB * NCH, CHSZ>>>();

    // h fastest: 8 sibling head-blocks of one (b,g) co-run and share token rows in L2
    cudaFuncSetAttribute(k_attn_mma, cudaFuncAttributeMaxDynamicSharedMemorySize, SMEM_ATT_BYTES);
    k_attn_mma<<<dim3(HH, NG, BB), 256, SMEM_ATT_BYTES>>>(qkv, logit_scale);

    cudaFuncSetAttribute(k_proj2, cudaFuncAttributeMaxDynamicSharedMemorySize, SMEM_PROJ_BYTES);
    k_proj2<<<dim3((BB * NN) / 128, CC / 128), 256, SMEM_PROJ_BYTES>>>(proj_b, out);
}